// round 1
// baseline (speedup 1.0000x reference)
#include <cuda_runtime.h>
#include <cuda_bf16.h>
#include <cstdint>

// Problem constants
#define CIN   256
#define KOUT  256
#define HH    56
#define WW    56
#define NPF   2304   // elements per output filter: 256*3*3

// Conv tiling
#define ROWS  4      // output rows per block
#define CB    8      // input-channel chunk
#define KT    64     // output channels per block
#define TK    8      // output channels per thread
#define TP    7      // pixels (cols) per thread

// Ternarized weights, transposed to [C][3][3][K] (k innermost) so conv-side
// global loads are coalesced and smem weight reads are warp-broadcast.
__device__ float g_wt[CIN * 9 * KOUT];

// ---------------------------------------------------------------------------
// Ternarize: one block per output filter o.
//   delta = 0.7/n * sum|w|;  alpha = sum(|w| where |w|>delta) / count
//   t = alpha * sign(w) where |w|>delta else 0
// ---------------------------------------------------------------------------
__global__ void ternarize_kernel(const float* __restrict__ w) {
    const int o = blockIdx.x;
    const int tid = threadIdx.x;
    const float* wo = w + (size_t)o * NPF;

    __shared__ float red[256];

    // pass 1: sum |w|
    float s = 0.f;
    for (int i = tid; i < NPF; i += 256) s += fabsf(wo[i]);
    red[tid] = s; __syncthreads();
    for (int st = 128; st > 0; st >>= 1) {
        if (tid < st) red[tid] += red[tid + st];
        __syncthreads();
    }
    const float delta = (0.7f / (float)NPF) * red[0];
    __syncthreads();

    // pass 2: count + masked abs-sum
    float cnt = 0.f, asum = 0.f;
    for (int i = tid; i < NPF; i += 256) {
        float a = fabsf(wo[i]);
        if (a > delta) { cnt += 1.f; asum += a; }
    }
    red[tid] = cnt; __syncthreads();
    for (int st = 128; st > 0; st >>= 1) {
        if (tid < st) red[tid] += red[tid + st];
        __syncthreads();
    }
    const float cnt_tot = red[0];
    __syncthreads();
    red[tid] = asum; __syncthreads();
    for (int st = 128; st > 0; st >>= 1) {
        if (tid < st) red[tid] += red[tid + st];
        __syncthreads();
    }
    const float alpha = red[0] / cnt_tot;
    __syncthreads();

    // pass 3: write ternarized weight, transposed layout [c*9+t][o]
    for (int i = tid; i < NPF; i += 256) {
        float v = wo[i];
        float t = (v > delta) ? alpha : ((v < -delta) ? -alpha : 0.f);
        g_wt[(size_t)i * KOUT + o] = t;
    }
}

// ---------------------------------------------------------------------------
// Direct conv, fp32 FMA.
// Block: 256 threads = 8 warps.
//   kg  = tid>>5        : 8 groups of TK=8 output channels  (KT = 64)
//   row = (tid&31)>>3   : 4 output rows
//   cg  = tid&7         : 8 groups of TP=7 output cols      (8*7 = 56 = full row)
// Grid: (56/ROWS = 14, KOUT/KT = 4, N = 32)
// Mainloop over input channels in chunks of CB=8:
//   smem input  : [CB][ROWS+2][60]   (58 valid cols, padded to 60)
//   smem weight : [CB][9][KT]        (k innermost -> broadcast LDS.128)
// Each thread: 56 accumulators, 9 input regs reused across 3 taps,
// weight reads are 2x float4 broadcast -> ~17 FFMA per LDS word.
// ---------------------------------------------------------------------------
__global__ __launch_bounds__(256, 2)
void conv_kernel(const float* __restrict__ x,
                 const float* __restrict__ bias,
                 float* __restrict__ out) {
    __shared__ float ish[CB][ROWS + 2][60];
    __shared__ float wsh[CB][9][KT];

    const int tid  = threadIdx.x;
    const int kg   = tid >> 5;
    const int lane = tid & 31;
    const int row  = lane >> 3;
    const int cg   = lane & 7;

    const int h0 = blockIdx.x * ROWS;
    const int k0 = blockIdx.y * KT;
    const int n  = blockIdx.z;

    float acc[TK][TP];
    #pragma unroll
    for (int i = 0; i < TK; i++)
        #pragma unroll
        for (int j = 0; j < TP; j++) acc[i][j] = 0.f;

    const float* xn = x + (size_t)n * CIN * HH * WW;
    float* wsh_flat = &wsh[0][0][0];

    for (int c0 = 0; c0 < CIN; c0 += CB) {
        __syncthreads();  // previous iteration's reads done

        // ---- load input tile: CB channels x 6 rows x 58 cols (+2 pad cols)
        for (int idx = tid; idx < CB * 6 * 60; idx += 256) {
            int c   = idx / 360;
            int rem = idx % 360;
            int rr  = rem / 60;
            int col = rem % 60;
            float v = 0.f;
            int gh = h0 - 1 + rr;
            int gw = col - 1;
            if (col < 58 && gh >= 0 && gh < HH && gw >= 0 && gw < WW)
                v = xn[((size_t)(c0 + c) * HH + gh) * WW + gw];
            ish[c][rr][col] = v;
        }

        // ---- load weight tile: coalesced (k innermost in g_wt)
        {
            const float* wptr = g_wt + (size_t)c0 * 9 * KOUT + k0;
            for (int idx = tid; idx < CB * 9 * KT; idx += 256) {
                wsh_flat[idx] = wptr[(size_t)(idx >> 6) * KOUT + (idx & 63)];
            }
        }
        __syncthreads();

        // ---- compute
        #pragma unroll 2
        for (int c = 0; c < CB; c++) {
            #pragma unroll
            for (int r = 0; r < 3; r++) {
                float in[TP + 2];
                const float* ip = &ish[c][row + r][cg * TP];
                #pragma unroll
                for (int j = 0; j < TP + 2; j++) in[j] = ip[j];

                #pragma unroll
                for (int s = 0; s < 3; s++) {
                    const float4* wp =
                        (const float4*)&wsh[c][r * 3 + s][kg * TK];
                    float4 w0 = wp[0];
                    float4 w1 = wp[1];
                    float wv[TK] = {w0.x, w0.y, w0.z, w0.w,
                                    w1.x, w1.y, w1.z, w1.w};
                    #pragma unroll
                    for (int kk = 0; kk < TK; kk++)
                        #pragma unroll
                        for (int p = 0; p < TP; p++)
                            acc[kk][p] = fmaf(wv[kk], in[s + p], acc[kk][p]);
                }
            }
        }
    }

    // ---- epilogue: add bias, store
    const int hout = h0 + row;
    #pragma unroll
    for (int kk = 0; kk < TK; kk++) {
        const int k = k0 + kg * TK + kk;
        const float b = bias[k];
        float* op = out + (((size_t)n * KOUT + k) * HH + hout) * WW + cg * TP;
        #pragma unroll
        for (int p = 0; p < TP; p++) op[p] = acc[kk][p] + b;
    }
}

extern "C" void kernel_launch(void* const* d_in, const int* in_sizes, int n_in,
                              void* d_out, int out_size) {
    const float* x      = (const float*)d_in[0];
    const float* weight = (const float*)d_in[1];
    const float* bias   = (const float*)d_in[2];
    float* out          = (float*)d_out;

    ternarize_kernel<<<KOUT, 256>>>(weight);

    dim3 grid(HH / ROWS, KOUT / KT, 32);
    conv_kernel<<<grid, 256>>>(x, bias, out);
}

// round 4
// speedup vs baseline: 5.4210x; 5.4210x over previous
#include <cuda_runtime.h>
#include <cuda_fp16.h>
#include <cstdint>

// ---------------- problem constants ----------------
#define CIN   256
#define KOUT  256
#define HH    56
#define WW    56
#define NPF   2304           // 256*3*3 per output filter
#define PH    58
#define PW    58
#define NIMG  32
#define PIX   (HH*WW)        // 3136
#define MTOT  (NIMG*PIX)     // 100352

// ---------------- GEMM tiling ----------------
#define MT    128            // CTA M tile
#define NT    128            // CTA N tile
#define KC    32             // K chunk (halfs)
#define NCH   72             // 9 taps * 8 chunks of 32 channels
#define NS    3              // pipeline stages

// smem: stage = A(128x32 @ stride 40 halfs) + B(128x32 @ stride 40)
#define ROWB  80             // bytes per smem row (40 halfs)
#define ASTG  (128*ROWB)     // 10240
#define STG   (2*ASTG)       // 20480
#define SMDYN (NS*STG)       // 61440

// ---------------- device scratch ----------------
__device__ __half g_b[9 * KOUT * CIN];                   // [rs][k][c], +-1
__device__ float  g_alpha[KOUT];
__device__ __half g_xpad[(size_t)NIMG * PH * PW * CIN];  // [n][hp][wp][c]

// ---------------- ptx helpers (family-portable only) ----------------
__device__ __forceinline__ void cp16(uint32_t dst, const void* src) {
    asm volatile("cp.async.cg.shared.global [%0], [%1], 16;"
                 :: "r"(dst), "l"(__cvta_generic_to_global(src)) : "memory");
}
#define CP_COMMIT()  asm volatile("cp.async.commit_group;" ::: "memory")
#define CP_WAIT(N)   asm volatile("cp.async.wait_group %0;" :: "n"(N) : "memory")

#define LDSM4(R, addr)                                                        \
    asm volatile("ldmatrix.sync.aligned.m8n8.x4.shared.b16 {%0,%1,%2,%3}, [%4];" \
                 : "=r"((R)[0]), "=r"((R)[1]), "=r"((R)[2]), "=r"((R)[3])     \
                 : "r"(addr))

#define MMA16816(D, A, B0, B1)                                                \
    asm volatile("mma.sync.aligned.m16n8k16.row.col.f32.f16.f16.f32 "         \
                 "{%0,%1,%2,%3}, {%4,%5,%6,%7}, {%8,%9}, {%0,%1,%2,%3};"      \
                 : "+f"((D)[0]), "+f"((D)[1]), "+f"((D)[2]), "+f"((D)[3])     \
                 : "r"((A)[0]), "r"((A)[1]), "r"((A)[2]), "r"((A)[3]),        \
                   "r"(B0), "r"(B1))

// ---------------------------------------------------------------------------
// K0: ternarize. One block per output filter o.
// ---------------------------------------------------------------------------
__global__ void ternarize_kernel(const float* __restrict__ w) {
    const int o = blockIdx.x;
    const int tid = threadIdx.x;
    const float* wo = w + (size_t)o * NPF;
    __shared__ float red[256];

    float s = 0.f;
    for (int i = tid; i < NPF; i += 256) s += fabsf(wo[i]);
    red[tid] = s; __syncthreads();
    for (int st = 128; st > 0; st >>= 1) {
        if (tid < st) red[tid] += red[tid + st];
        __syncthreads();
    }
    const float delta = (0.7f / (float)NPF) * red[0];
    __syncthreads();

    float cnt = 0.f, asum = 0.f;
    for (int i = tid; i < NPF; i += 256) {
        float a = fabsf(wo[i]);
        if (a > delta) { cnt += 1.f; asum += a; }
    }
    red[tid] = cnt; __syncthreads();
    for (int st = 128; st > 0; st >>= 1) {
        if (tid < st) red[tid] += red[tid + st];
        __syncthreads();
    }
    const float cnt_tot = red[0];
    __syncthreads();
    red[tid] = asum; __syncthreads();
    for (int st = 128; st > 0; st >>= 1) {
        if (tid < st) red[tid] += red[tid + st];
        __syncthreads();
    }
    const float alpha = red[0] / cnt_tot;

    for (int i = tid; i < NPF; i += 256) {
        float v = wo[i];
        float t = (v > delta) ? 1.f : ((v < -delta) ? -1.f : 0.f);
        int c = i / 9, rs = i % 9;
        g_b[((size_t)rs * KOUT + o) * CIN + c] = __float2half_rn(t);
    }
    if (tid == 0) g_alpha[o] = alpha;
}

// ---------------------------------------------------------------------------
// K1: zero padded rows hp=0, hp=57 of g_xpad.
// ---------------------------------------------------------------------------
__global__ void zero_pad_kernel() {
    int i = blockIdx.x * 256 + threadIdx.x;
    int n = i / (2 * 1856);
    int r = i - n * 2 * 1856;
    int which = r / 1856;
    int off = r - which * 1856;
    size_t hp = which ? (PH - 1) : 0;
    uint4* p = (uint4*)(g_xpad + ((size_t)n * PH + hp) * PW * CIN);
    p[off] = make_uint4(0u, 0u, 0u, 0u);
}

// ---------------------------------------------------------------------------
// K2: pad + NCHW->NHWC transpose + fp16 convert.
// ---------------------------------------------------------------------------
__global__ void pad_transpose_kernel(const float* __restrict__ x) {
    __shared__ float s[64][57];
    const int h = blockIdx.x, c0 = blockIdx.y * 64, n = blockIdx.z;
    const float* xp = x + ((size_t)(n * CIN + c0) * HH + h) * WW;

    for (int idx = threadIdx.x; idx < 64 * WW; idx += 256) {
        int ci = idx / WW, w = idx - ci * WW;
        s[ci][w] = xp[(size_t)ci * PIX + w];
    }
    __syncthreads();

    __half* dst = g_xpad + ((size_t)(n * PH + (h + 1)) * PW) * CIN + c0;
    for (int idx = threadIdx.x; idx < PW * 64; idx += 256) {
        int wp = idx / 64, ci = idx - wp * 64;
        float v = (wp >= 1 && wp <= WW) ? s[ci][wp - 1] : 0.f;
        dst[(size_t)wp * CIN + ci] = __float2half_rn(v);
    }
}

// ---------------------------------------------------------------------------
// K3: implicit-GEMM conv via mma.sync m16n8k16 (family-portable tensor path).
// Grid (784, 2): CTA = 128 pixels x 128 out channels. 8 warps, warp 64x32.
// ---------------------------------------------------------------------------
__global__ void __launch_bounds__(256)
conv_mma_kernel(const float* __restrict__ bias_g, float* __restrict__ out) {
    extern __shared__ __align__(128) char smem[];
    const uint32_t sb = (uint32_t)__cvta_generic_to_shared(smem);

    const int tid = threadIdx.x;
    const int lane = tid & 31;
    const int wid = tid >> 5;
    const int warp_m = wid >> 2;   // 0..1
    const int warp_n = wid & 3;    // 0..3

    const int p0 = blockIdx.x * MT;
    const int n0 = blockIdx.y * NT;

    __shared__ float s_alpha[128], s_bias[128];
    if (tid < 128) s_alpha[tid] = g_alpha[n0 + tid];
    else           s_bias[tid - 128] = bias_g[n0 + tid - 128];

    // ---- per-thread cp.async source/dest precompute ----
    // each thread: 2 A rows (row, row+64) and 2 B rows, 16B segment each
    const int seg = tid & 3;               // 16B segment of 64B row
    const int arow = tid >> 2;             // 0..63
    const __half* a_g[2];
    #pragma unroll
    for (int q = 0; q < 2; q++) {
        int row = arow + q * 64;
        int p = p0 + row;
        int n = p / PIX; int rem = p - n * PIX;
        int h = rem / WW; int w = rem - h * WW;
        a_g[q] = g_xpad + ((size_t)((n * PH + h) * PW + w)) * CIN + seg * 8;
    }
    const __half* b_g[2];
    #pragma unroll
    for (int q = 0; q < 2; q++)
        b_g[q] = g_b + (size_t)(n0 + arow + q * 64) * CIN + seg * 8;
    const uint32_t s_off0 = (uint32_t)(arow * ROWB + seg * 16);
    const uint32_t s_off1 = s_off0 + 64 * ROWB;

    // ---- ldmatrix address precompute (byte offsets within stage) ----
    uint32_t a_lm[4];
    {
        int rr = lane & 15;
        int ch = (lane >> 4) * 8;  // half offset
        #pragma unroll
        for (int i = 0; i < 4; i++)
            a_lm[i] = (uint32_t)((warp_m * 64 + i * 16 + rr) * ROWB + ch * 2);
    }
    uint32_t b_lm[2];
    {
        int nn = (lane & 7) + ((lane & 16) >> 1);
        int kk0 = lane & 8;        // half offset
        #pragma unroll
        for (int j = 0; j < 2; j++)
            b_lm[j] = (uint32_t)((warp_n * 32 + j * 16 + nn) * ROWB + kk0 * 2);
    }

    float acc[4][4][4];
    #pragma unroll
    for (int i = 0; i < 4; i++)
        #pragma unroll
        for (int j = 0; j < 4; j++)
            #pragma unroll
            for (int r = 0; r < 4; r++) acc[i][j][r] = 0.f;

    auto fill = [&](int st, int ch) {
        int rs = ch >> 3, cc = ch & 7;
        int r = rs / 3, s = rs - r * 3;
        size_t aoff = (size_t)((r * PW + s) * CIN + cc * KC);
        size_t boff = (size_t)rs * (KOUT * CIN) + cc * KC;
        uint32_t ab = sb + st * STG;
        uint32_t bb = ab + ASTG;
        cp16(ab + s_off0, a_g[0] + aoff);
        cp16(ab + s_off1, a_g[1] + aoff);
        cp16(bb + s_off0, b_g[0] + boff);
        cp16(bb + s_off1, b_g[1] + boff);
        CP_COMMIT();
    };

    // ---- pipelined mainloop ----
    fill(0, 0);
    fill(1, 1);

    int st = 0;
    for (int ch = 0; ch < NCH; ch++) {
        CP_WAIT(1);
        __syncthreads();
        if (ch + 2 < NCH) fill((st + 2) % NS, ch + 2);
        else              CP_COMMIT();

        uint32_t ab = sb + st * STG;
        uint32_t bb = ab + ASTG;
        #pragma unroll
        for (int kk = 0; kk < 2; kk++) {
            uint32_t a[4][4], b[2][4];
            #pragma unroll
            for (int i = 0; i < 4; i++) LDSM4(a[i], ab + a_lm[i] + kk * 32);
            #pragma unroll
            for (int j = 0; j < 2; j++) LDSM4(b[j], bb + b_lm[j] + kk * 32);
            #pragma unroll
            for (int i = 0; i < 4; i++)
                #pragma unroll
                for (int j2 = 0; j2 < 4; j2++)
                    MMA16816(acc[i][j2], a[i],
                             b[j2 >> 1][(j2 & 1) * 2],
                             b[j2 >> 1][(j2 & 1) * 2 + 1]);
        }
        st++; if (st == NS) st = 0;
    }
    CP_WAIT(0);
    __syncthreads();

    // ---- epilogue: stage through smem, out = alpha*acc + bias ----
    float* stile = (float*)smem;   // [128][65]
    const int m_ep = tid & 127;
    const int kb = tid >> 7;       // 0/1
    int p = p0 + m_ep;
    int nimg = p / PIX; int hw = p - nimg * PIX;

    #pragma unroll
    for (int phase = 0; phase < 2; phase++) {
        #pragma unroll
        for (int i = 0; i < 4; i++)
            #pragma unroll
            for (int j2 = 0; j2 < 4; j2++) {
                int nl = warp_n * 32 + j2 * 8 + (lane & 3) * 2;
                if ((nl >> 6) == phase) {
                    int no = nl & 63;
                    int m0 = warp_m * 64 + i * 16 + (lane >> 2);
                    stile[m0 * 65 + no]           = acc[i][j2][0];
                    stile[m0 * 65 + no + 1]       = acc[i][j2][1];
                    stile[(m0 + 8) * 65 + no]     = acc[i][j2][2];
                    stile[(m0 + 8) * 65 + no + 1] = acc[i][j2][3];
                }
            }
        __syncthreads();

        float* ob = out + ((size_t)nimg * KOUT + n0 + phase * 64) * PIX + hw;
        #pragma unroll
        for (int it = 0; it < 32; it++) {
            int k = it * 2 + kb;
            int kg = phase * 64 + k;
            float v = stile[m_ep * 65 + k];
            ob[(size_t)k * PIX] = fmaf(s_alpha[kg], v, s_bias[kg]);
        }
        __syncthreads();
    }
}

// ---------------------------------------------------------------------------
extern "C" void kernel_launch(void* const* d_in, const int* in_sizes, int n_in,
                              void* d_out, int out_size) {
    const float* x      = (const float*)d_in[0];
    const float* weight = (const float*)d_in[1];
    const float* bias   = (const float*)d_in[2];
    float* out          = (float*)d_out;

    cudaFuncSetAttribute(conv_mma_kernel,
                         cudaFuncAttributeMaxDynamicSharedMemorySize, SMDYN);

    ternarize_kernel<<<KOUT, 256>>>(weight);
    zero_pad_kernel<<<464, 256>>>();
    pad_transpose_kernel<<<dim3(HH, 4, NIMG), 256>>>(x);
    conv_mma_kernel<<<dim3(MTOT / MT, KOUT / NT), 256, SMDYN>>>(bias, out);
}